// round 5
// baseline (speedup 1.0000x reference)
#include <cuda_runtime.h>
#include <cstdint>

namespace {
constexpr int Sc = 1024, Dc = 64, BH = 128;
constexpr int TQ = 16, NT = 256, KT = 64;
constexpr int SQ_P = 68;
constexpr int SS_P = 1028;
constexpr int KP   = 68;            // K tile pitch (272B rows, 16B multiple)
constexpr int VP   = 72;            // V tile pitch (288B rows, 16B multiple)
constexpr int BUF  = KT * VP;       // 4608 floats per buffer (K uses KP rows)
constexpr int SMEM_FLOATS = 8 + TQ * SS_P + TQ * SQ_P + 2 * BUF;  // 26760
constexpr size_t ATTN_OFF = (size_t)BH * Sc * Dc;
}

__device__ __forceinline__ float to_tf32(float x) {
    uint32_t u;
    asm("cvt.rna.tf32.f32 %0, %1;" : "=r"(u) : "f"(x));
    return __uint_as_float(u);
}

__device__ __forceinline__ void mma8(float c[4],
                                     float a0, float a1, float a2, float a3,
                                     float b0, float b1) {
    asm volatile(
        "mma.sync.aligned.m16n8k8.row.col.f32.tf32.tf32.f32 "
        "{%0,%1,%2,%3}, {%4,%5,%6,%7}, {%8,%9}, {%0,%1,%2,%3};\n"
        : "+f"(c[0]), "+f"(c[1]), "+f"(c[2]), "+f"(c[3])
        : "r"(__float_as_uint(a0)), "r"(__float_as_uint(a1)),
          "r"(__float_as_uint(a2)), "r"(__float_as_uint(a3)),
          "r"(__float_as_uint(b0)), "r"(__float_as_uint(b1)));
}

__device__ __forceinline__ uint32_t s2u(const void* p) {
    uint32_t a;
    asm("{ .reg .u64 t; cvta.to.shared.u64 t, %1; cvt.u32.u64 %0, t; }"
        : "=r"(a) : "l"(p));
    return a;
}

__device__ __forceinline__ void mbar_init(uint32_t m, uint32_t cnt) {
    asm volatile("mbarrier.init.shared.b64 [%0], %1;" :: "r"(m), "r"(cnt) : "memory");
}
__device__ __forceinline__ void mbar_arrive(uint32_t m) {
    asm volatile("mbarrier.arrive.shared.b64 _, [%0];" :: "r"(m) : "memory");
}
__device__ __forceinline__ void mbar_wait(uint32_t m, uint32_t parity) {
    asm volatile(
        "{\n\t.reg .pred P;\n"
        "W%=:\n\t"
        "mbarrier.try_wait.parity.acquire.cta.shared::cta.b64 P, [%0], %1, 0x989680;\n\t"
        "@P bra D%=;\n\t"
        "bra W%=;\n"
        "D%=:\n\t}"
        :: "r"(m), "r"(parity) : "memory");
}
// producer: arrive+expect 256B on full barrier, then bulk-copy one 256B row
__device__ __forceinline__ void bulk_row(uint32_t mbar, uint32_t dst,
                                         const float* src) {
    asm volatile("mbarrier.arrive.expect_tx.shared.b64 _, [%0], %1;"
                 :: "r"(mbar), "r"(256) : "memory");
    asm volatile(
        "cp.async.bulk.shared::cluster.global.mbarrier::complete_tx::bytes "
        "[%0], [%1], 256, [%2];"
        :: "r"(dst), "l"(src), "r"(mbar) : "memory");
}

__global__ void __launch_bounds__(NT, 2)
attn_tf32_kernel(const float* __restrict__ Qg_, const float* __restrict__ Kg_,
                 const float* __restrict__ Vg_, const int* __restrict__ Mg_,
                 float* __restrict__ out)
{
    extern __shared__ float sm[];
    float* sS  = sm + 8;                  // [TQ][SS_P]
    float* sQ  = sS + TQ * SS_P;          // [TQ][SQ_P]
    float* sKV = sQ + TQ * SQ_P;          // [2][BUF], raw fp32 K/V tiles

    const uint32_t mb = s2u(sm);
    const uint32_t kvu = s2u(sKV);
    // barriers: full[2] at mb+0/mb+8, empty[2] at mb+16/mb+24

    const int qt = blockIdx.x, bh = blockIdx.y, b = bh >> 4;
    const int tid = threadIdx.x, warp = tid >> 5, lane = tid & 31;
    const int gid = lane >> 2, tig = lane & 3, w8 = warp << 3;

    const float* Qg = Qg_ + ((size_t)bh * Sc + (size_t)qt * TQ) * Dc;
    const float* Kg = Kg_ + (size_t)bh * Sc * Dc;
    const float* Vg = Vg_ + (size_t)bh * Sc * Dc;
    float* outO = out + ((size_t)bh * Sc + (size_t)qt * TQ) * Dc;
    float* outA = out + ATTN_OFF + ((size_t)bh * Sc + (size_t)qt * TQ) * Sc;
    const int* Mg = Mg_ + ((size_t)b * Sc + (size_t)qt * TQ) * Sc;

    if (tid == 0) {
        mbar_init(mb, 64);      mbar_init(mb + 8, 64);       // full
        mbar_init(mb + 16, NT); mbar_init(mb + 24, NT);      // empty
    }
    {   // Q tile -> smem, *1/8, tf32
        int row = tid >> 4, c4 = tid & 15;
        float4 v = reinterpret_cast<const float4*>(Qg)[tid];
        float* dst = sQ + row * SQ_P + c4 * 4;
        dst[0] = to_tf32(v.x * 0.125f); dst[1] = to_tf32(v.y * 0.125f);
        dst[2] = to_tf32(v.z * 0.125f); dst[3] = to_tf32(v.w * 0.125f);
    }
    __syncthreads();

    // stage s: 0..15 = K tile s, 16..31 = V tile s-16; buffer = s&1
    auto issue = [&](int s) {
        int bb = s & 1;
        uint32_t fb = mb + bb * 8;
        uint32_t dst = kvu + bb * (BUF * 4);
        if (s < 16)
            bulk_row(fb, dst + tid * (KP * 4),
                     Kg + (size_t)s * KT * Dc + (size_t)tid * Dc);
        else
            bulk_row(fb, dst + tid * (VP * 4),
                     Vg + (size_t)(s - 16) * KT * Dc + (size_t)tid * Dc);
    };
    if (tid < 64) { issue(0); issue(1); }

    // A fragments (Q), reused across all 16 K tiles
    float aq[8][4];
#pragma unroll
    for (int ks = 0; ks < 8; ks++) {
        const float* p = sQ + gid * SQ_P + ks * 8 + tig;
        aq[ks][0] = p[0];           aq[ks][1] = p[8 * SQ_P];
        aq[ks][2] = p[4];           aq[ks][3] = p[8 * SQ_P + 4];
    }

    // ---------------- GEMM1: scores = (Q/8) @ K^T --------------------------
    for (int kt = 0; kt < 16; kt++) {
        int bb = kt & 1;
        uint32_t u = kt >> 1;                 // use index of this buffer
        mbar_wait(mb + bb * 8, u & 1);        // full
        const float* kb = sKV + bb * BUF;

        float cA[4] = {0,0,0,0}, cB[4] = {0,0,0,0};
#pragma unroll
        for (int ks = 0; ks < 8; ks += 2) {
            const float* bp0 = kb + (w8 + gid) * KP + ks * 8 + tig;
            mma8(cA, aq[ks][0], aq[ks][1], aq[ks][2], aq[ks][3],
                 to_tf32(bp0[0]), to_tf32(bp0[4]));
            const float* bp1 = bp0 + 8;
            mma8(cB, aq[ks+1][0], aq[ks+1][1], aq[ks+1][2], aq[ks+1][3],
                 to_tf32(bp1[0]), to_tf32(bp1[4]));
        }
        int col = kt * KT + w8 + tig * 2;
        float* p  = sS + gid * SS_P + col;
        float* p2 = p + 8 * SS_P;
        p[0]  = cA[0] + cB[0]; p[1]  = cA[1] + cB[1];
        p2[0] = cA[2] + cB[2]; p2[1] = cA[3] + cB[3];

        mbar_arrive(mb + 16 + bb * 8);        // empty
        if (tid < 64) {                        // refill with stage kt+2
            mbar_wait(mb + 16 + bb * 8, u & 1);
            issue(kt + 2);
        }
    }
    __syncthreads();

    // ---------------- softmax + post-softmax mask + attn write -------------
#pragma unroll
    for (int rr = 0; rr < 2; rr++) {
        int row = warp * 2 + rr;
        float4* srow4 = reinterpret_cast<float4*>(sS + row * SS_P);

        float mx = -3.0e38f;
#pragma unroll
        for (int i = 0; i < 8; i++) {
            float4 v = srow4[lane + i * 32];
            mx = fmaxf(mx, fmaxf(fmaxf(v.x, v.y), fmaxf(v.z, v.w)));
        }
#pragma unroll
        for (int o = 16; o > 0; o >>= 1)
            mx = fmaxf(mx, __shfl_xor_sync(0xffffffffu, mx, o));

        float sum = 0.f;
        float4 e[8];
#pragma unroll
        for (int i = 0; i < 8; i++) {
            float4 v = srow4[lane + i * 32];
            v.x = __expf(v.x - mx); v.y = __expf(v.y - mx);
            v.z = __expf(v.z - mx); v.w = __expf(v.w - mx);
            e[i] = v;
            sum += (v.x + v.y) + (v.z + v.w);
        }
#pragma unroll
        for (int o = 16; o > 0; o >>= 1)
            sum += __shfl_xor_sync(0xffffffffu, sum, o);
        float inv = 1.0f / sum;

        const int4* mrow = reinterpret_cast<const int4*>(Mg + (size_t)row * Sc);
        float4* arow = reinterpret_cast<float4*>(outA + (size_t)row * Sc);
#pragma unroll
        for (int i = 0; i < 8; i++) {
            int idx = lane + i * 32;
            int4 m = mrow[idx];
            float4 w;
            w.x = m.x ? e[i].x * inv : -100000.0f;
            w.y = m.y ? e[i].y * inv : -100000.0f;
            w.z = m.z ? e[i].z * inv : -100000.0f;
            w.w = m.w ? e[i].w * inv : -100000.0f;
            __stcs(&arow[idx], w);
            float4 t;
            t.x = to_tf32(w.x); t.y = to_tf32(w.y);
            t.z = to_tf32(w.z); t.w = to_tf32(w.w);
            srow4[idx] = t;
        }
    }
    __syncthreads();

    // ---------------- GEMM2: out = attn @ V (n-split, TMA-fed) -------------
    float c2A[4] = {0,0,0,0}, c2B[4] = {0,0,0,0};
    for (int vt = 0; vt < 16; vt++) {
        int bb = vt & 1;
        uint32_t u = 8 + (vt >> 1);           // use index of this buffer
        mbar_wait(mb + bb * 8, u & 1);        // full
        const float* vb = sKV + bb * BUF;

#pragma unroll
        for (int ks = 0; ks < 8; ks += 2) {
            const float* ap0 = sS + gid * SS_P + vt * KT + ks * 8 + tig;
            float a00 = ap0[0],        a01 = ap0[8 * SS_P];
            float a02 = ap0[4],        a03 = ap0[8 * SS_P + 4];
            const float* bp0 = vb + (ks * 8 + tig) * VP + w8 + gid;
            mma8(c2A, a00, a01, a02, a03,
                 to_tf32(bp0[0]), to_tf32(bp0[4 * VP]));

            const float* ap1 = ap0 + 8;
            float a10 = ap1[0],        a11 = ap1[8 * SS_P];
            float a12 = ap1[4],        a13 = ap1[8 * SS_P + 4];
            const float* bp1 = vb + ((ks + 1) * 8 + tig) * VP + w8 + gid;
            mma8(c2B, a10, a11, a12, a13,
                 to_tf32(bp1[0]), to_tf32(bp1[4 * VP]));
        }
        mbar_arrive(mb + 16 + bb * 8);        // empty
        if (tid < 64 && vt < 14) {
            mbar_wait(mb + 16 + bb * 8, u & 1);
            issue(vt + 18);
        }
    }

    {
        int col = w8 + tig * 2;
        float* p  = outO + gid * Dc + col;
        float* p2 = outO + (gid + 8) * Dc + col;
        p[0]  = c2A[0] + c2B[0]; p[1]  = c2A[1] + c2B[1];
        p2[0] = c2A[2] + c2B[2]; p2[1] = c2A[3] + c2B[3];
    }
}

extern "C" void kernel_launch(void* const* d_in, const int* in_sizes, int n_in,
                              void* d_out, int out_size)
{
    (void)in_sizes; (void)n_in; (void)out_size;
    const float* Q = (const float*)d_in[0];
    const float* K = (const float*)d_in[1];
    const float* V = (const float*)d_in[2];
    const int*   M = (const int*)d_in[3];
    float* out = (float*)d_out;

    cudaFuncSetAttribute(attn_tf32_kernel,
                         cudaFuncAttributeMaxDynamicSharedMemorySize,
                         SMEM_FLOATS * (int)sizeof(float));
    dim3 grid(Sc / TQ, BH);
    attn_tf32_kernel<<<grid, NT, SMEM_FLOATS * sizeof(float)>>>(Q, K, V, M, out);
}